// round 16
// baseline (speedup 1.0000x reference)
#include <cuda_runtime.h>

// Inverted index scratch. g_head[row]: 0 = empty, else eid+1.
// g_next[eid]: 0 = end, else next_eid+1.  eid = b*Kp1 + k == output offset.
// g_head is zero at module load; the fused kernel's epilogue resets every
// head it consumed back to 0, so each launch (and graph replay) starts clean.
#define MAX_N (1 << 20)        // >= 1,000,000 rows
#define MAX_E (1 << 21)        // >= 1,048,832 entries
__device__ int g_head[MAX_N];
__device__ int g_next[MAX_E];

// Non-forwardable LDS: compiler cannot CSE this back to the registers that
// produced the stashed values, so the copy-phase v[] truly dies at the stores.
__device__ __forceinline__ float4 lds_f4_fresh(const float4* p) {
    float4 r;
    unsigned saddr = (unsigned)__cvta_generic_to_shared(p);
    asm volatile("ld.shared.v4.f32 {%0,%1,%2,%3}, [%4];"
                 : "=f"(r.x), "=f"(r.y), "=f"(r.z), "=f"(r.w)
                 : "r"(saddr));
    return r;
}

// ----------------------------------------------------------------------------
// Kernel B: bin score entries into per-row chains (scalar — proven fastest).
// Fires the PDL trigger at entry so the fused kernel can begin its copy
// phase concurrently.
// ----------------------------------------------------------------------------
__global__ void bin_kernel(const int* __restrict__ idx, int E) {
    cudaTriggerProgrammaticLaunchCompletion();
    int eid = blockIdx.x * blockDim.x + threadIdx.x;
    if (eid >= E) return;
    int row = idx[eid];
    g_next[eid] = atomicExch(&g_head[row], eid + 1);
}

// ----------------------------------------------------------------------------
// Kernel C: fused copy + scores + positive momentum update.
// One warp per RPW=2 consecutive rows (proven sweet spot: regs 32, MLP=2).
// PDL secondary: Phase-1 copy traffic (loads/stores/stash) issues BEFORE
// cudaGridDependencySynchronize(), overlapping the bin kernel; only the
// g_head/g_next consumption waits for bin completion.
// ----------------------------------------------------------------------------
#define RPW 2

template <int KP1C, bool EXACT>
__global__ void __launch_bounds__(256, 8)
fused_copy_score_kernel(const float4* __restrict__ mem4,
                        float4* __restrict__ dst4,
                        const float4* __restrict__ x4,
                        float* __restrict__ out,
                        int N, int Kp1_rt, float invT) {
    const int Kp1 = (KP1C > 0) ? KP1C : Kp1_rt;
    const int lane = threadIdx.x & 31;
    const int wlocal = threadIdx.x >> 5;                 // 0..7
    const int wg = (blockIdx.x * blockDim.x + threadIdx.x) >> 5;
    const int r0 = wg * RPW;
    if (!EXACT && r0 >= N) {
        cudaGridDependencySynchronize();
        return;
    }

    // 8 warps x 2 rows x 32 lanes x 16B = 8 KB
    __shared__ float4 stash[8 * RPW * 32];
    float4* my = &stash[wlocal * (RPW * 32) + lane];

    const float4* __restrict__ src = mem4 + (size_t)r0 * 32 + lane;
    float4*       __restrict__ dst = dst4 + (size_t)r0 * 32 + lane;

    // ---- Phase 1: pure copy stream + smem stash (independent of bin) ----
    {
        float4 v[RPW];
        #pragma unroll
        for (int j = 0; j < RPW; j++) {
            if (EXACT || r0 + j < N) v[j] = src[j * 32];   // LDG.128
        }
        #pragma unroll
        for (int j = 0; j < RPW; j++) {
            if (EXACT || r0 + j < N) dst[j * 32] = v[j];   // STG.128
        }
        #pragma unroll
        for (int j = 0; j < RPW; j++) {
            my[j * 32] = v[j];                             // STS.128
        }
    }   // v[] dead here

    // ---- Wait for bin kernel before touching the inverted index ----
    cudaGridDependencySynchronize();

    int hd[RPW];
    #pragma unroll
    for (int j = 0; j < RPW; j++) {
        hd[j] = (EXACT || r0 + j < N) ? g_head[r0 + j] : 0;
    }

    // ---- Early out only if EVERY row in the group is empty (~12%) ----
    int any = 0;
    #pragma unroll
    for (int j = 0; j < RPW; j++) any |= hd[j];
    if (any == 0) return;            // heads already 0; no reset needed

    int posb[RPW];
    #pragma unroll
    for (int j = 0; j < RPW; j++) posb[j] = -1;

    // ---- First entries: batched, full ILP, single interleaved reduction ----
    int e[RPW], nxt[RPW];
    float s[RPW];
    #pragma unroll
    for (int j = 0; j < RPW; j++) {
        e[j] = hd[j];
        nxt[j] = (e[j] > 0) ? g_next[e[j] - 1] : 0;
    }
    #pragma unroll
    for (int j = 0; j < RPW; j++) {
        if (e[j] > 0) {
            unsigned int b = (unsigned int)(e[j] - 1) / (unsigned int)Kp1;
            float4 xv = x4[b * 32 + lane];                 // L1/L2-resident
            float4 rv = lds_f4_fresh(my + j * 32);         // independent LDS
            s[j] = rv.x * xv.x + rv.y * xv.y
                 + rv.z * xv.z + rv.w * xv.w;
        } else {
            s[j] = 0.0f;
        }
    }
    #pragma unroll
    for (int o = 16; o > 0; o >>= 1) {
        #pragma unroll
        for (int j = 0; j < RPW; j++) {
            s[j] += __shfl_xor_sync(0xffffffffu, s[j], o);
        }
    }
    #pragma unroll
    for (int j = 0; j < RPW; j++) {
        if (e[j] > 0) {
            int eid = e[j] - 1;
            unsigned int b = (unsigned int)eid / (unsigned int)Kp1;
            int k = eid - (int)b * Kp1;
            if (lane == 0) out[eid] = s[j] * invT;
            if (k == 0) posb[j] = max(posb[j], (int)b);
        }
    }

    // ---- Continuation for chains of length >= 2 (rare) ----
    #pragma unroll
    for (int j = 0; j < RPW; j++) {
        int ee = nxt[j];
        while (ee > 0) {
            int eid = ee - 1;
            unsigned int b = (unsigned int)eid / (unsigned int)Kp1;
            int k = eid - (int)b * Kp1;
            float4 xv = x4[b * 32 + lane];
            float4 rv = lds_f4_fresh(my + j * 32);
            float ss = rv.x * xv.x + rv.y * xv.y
                     + rv.z * xv.z + rv.w * xv.w;
            #pragma unroll
            for (int o = 16; o > 0; o >>= 1)
                ss += __shfl_xor_sync(0xffffffffu, ss, o);
            if (lane == 0) out[eid] = ss * invT;
            if (k == 0) posb[j] = max(posb[j], (int)b);
            ee = g_next[eid];
        }
    }

    // ---- Momentum update overwrite (~256 rows grid-wide) ----
    #pragma unroll
    for (int j = 0; j < RPW; j++) {
        if (posb[j] >= 0) {
            float4 xv = x4[posb[j] * 32 + lane];
            float4 rv = lds_f4_fresh(my + j * 32);
            float4 w;
            w.x = 0.5f * rv.x + 0.5f * xv.x;
            w.y = 0.5f * rv.y + 0.5f * xv.y;
            w.z = 0.5f * rv.z + 0.5f * xv.z;
            w.w = 0.5f * rv.w + 0.5f * xv.w;
            float ss = w.x * w.x + w.y * w.y + w.z * w.z + w.w * w.w;
            #pragma unroll
            for (int o = 16; o > 0; o >>= 1)
                ss += __shfl_xor_sync(0xffffffffu, ss, o);
            float inv = 1.0f / sqrtf(ss);
            w.x *= inv; w.y *= inv; w.z *= inv; w.w *= inv;
            dst[j * 32] = w;
        }
    }

    // ---- Reset this warp's heads for the next launch / graph replay ----
    if (lane < RPW) {
        if (EXACT || r0 + lane < N) g_head[r0 + lane] = 0;
    }
}

// ----------------------------------------------------------------------------
// Launch. Inputs: x [B,D] f32, memory [N,D] f32, y [B] i32, idx [B,K+1] i32.
// Output: out [B,K+1] f32 then new_memory [N,D] f32.
// ----------------------------------------------------------------------------
extern "C" void kernel_launch(void* const* d_in, const int* in_sizes, int n_in,
                              void* d_out, int out_size) {
    const float* x      = (const float*)d_in[0];
    const float* memory = (const float*)d_in[1];
    const int*   idx    = (const int*)d_in[3];

    int B   = in_sizes[2];                  // 256
    int D   = in_sizes[0] / B;              // 128
    int Kp1 = in_sizes[3] / B;              // 4097
    int N   = in_sizes[1] / D;              // 1,000,000
    int E   = in_sizes[3];                  // B*Kp1 = 1,048,832

    float* out_scores = (float*)d_out;
    float* new_memory = (float*)d_out + (long long)E;

    const float invT = 1.0f / 0.07f;

    // B) bin score entries by memory row (PDL primary; trigger fires at entry)
    bin_kernel<<<(E + 255) / 256, 256>>>(idx, E);

    // C) fused copy + scores + positive update — PDL secondary: launches
    //    while bin runs; syncs on bin completion only before index reads.
    {
        int threads = 256;                           // 8 warps/block
        int rows_per_block = (threads / 32) * RPW;   // 16
        int blocks = (N + rows_per_block - 1) / rows_per_block;
        bool exact = (N % rows_per_block) == 0;      // 1e6 / 16 = 62500 exact

        cudaLaunchConfig_t cfg = {};
        cfg.gridDim = dim3((unsigned)blocks, 1, 1);
        cfg.blockDim = dim3((unsigned)threads, 1, 1);
        cfg.dynamicSmemBytes = 0;
        cfg.stream = 0;
        cudaLaunchAttribute attrs[1];
        attrs[0].id = cudaLaunchAttributeProgrammaticStreamSerialization;
        attrs[0].val.programmaticStreamSerializationAllowed = 1;
        cfg.attrs = attrs;
        cfg.numAttrs = 1;

        if (Kp1 == 4097 && exact) {
            cudaLaunchKernelEx(&cfg, fused_copy_score_kernel<4097, true>,
                               (const float4*)memory, (float4*)new_memory,
                               (const float4*)x, out_scores, N, Kp1, invT);
        } else if (exact) {
            cudaLaunchKernelEx(&cfg, fused_copy_score_kernel<0, true>,
                               (const float4*)memory, (float4*)new_memory,
                               (const float4*)x, out_scores, N, Kp1, invT);
        } else {
            cudaLaunchKernelEx(&cfg, fused_copy_score_kernel<0, false>,
                               (const float4*)memory, (float4*)new_memory,
                               (const float4*)x, out_scores, N, Kp1, invT);
        }
    }
}